// round 2
// baseline (speedup 1.0000x reference)
#include <cuda_runtime.h>
#include <cuda_bf16.h>

// Problem constants (fixed by dataset)
constexpr int Bb = 8;
constexpr int Nn = 8192;
constexpr int Mm = 2048;
constexpr int Cc = 64;
constexpr int Kk = 32;

// Scratch: transposed feature (B, N, C) and per-point squared norms
__device__ float g_feat_t[Bb * Nn * Cc];   // 16.8 MB
__device__ float g_n2[Bb * Nn];            // 256 KB

// ---------------------------------------------------------------------------
// Kernel 1: transpose feature (B,C,N) -> (B,N,C), and compute n2 per point
// ---------------------------------------------------------------------------
__global__ void transpose_kernel(const float* __restrict__ feat) {
    __shared__ float tile[32][33];
    int b  = blockIdx.z;
    int n0 = blockIdx.x * 32;
    int c0 = blockIdx.y * 32;
    // read feat[b, c0+i, n0+tx], coalesced over n
    for (int i = threadIdx.y; i < 32; i += 8) {
        tile[i][threadIdx.x] = feat[((size_t)(b * Cc + c0 + i)) * Nn + n0 + threadIdx.x];
    }
    __syncthreads();
    // write feat_t[b, n0+i, c0+tx], coalesced over c
    for (int i = threadIdx.y; i < 32; i += 8) {
        g_feat_t[((size_t)(b * Nn + n0 + i)) * Cc + c0 + threadIdx.x] = tile[threadIdx.x][i];
    }
}

__global__ void n2_kernel(const float* __restrict__ xyz) {
    int t = blockIdx.x * blockDim.x + threadIdx.x;   // 0 .. B*N-1
    if (t >= Bb * Nn) return;
    int b = t / Nn;
    int n = t - b * Nn;
    float x = xyz[(b * 3 + 0) * Nn + n];
    float y = xyz[(b * 3 + 1) * Nn + n];
    float z = xyz[(b * 3 + 2) * Nn + n];
    // match reference rounding: ((x*x + y*y) + z*z), no FMA contraction
    g_n2[t] = __fadd_rn(__fadd_rn(__fmul_rn(x, x), __fmul_rn(y, y)), __fmul_rn(z, z));
}

// ---------------------------------------------------------------------------
// Kernel 2: fused ball-query + grouping.  One block (256 thr) per (b, m).
// ---------------------------------------------------------------------------
__global__ __launch_bounds__(256) void group_kernel(
    const float* __restrict__ new_xyz,
    const float* __restrict__ xyz,
    float* __restrict__ out)
{
    const int bm   = blockIdx.x;
    const int b    = bm >> 11;         // / 2048
    const int m    = bm & (Mm - 1);
    const int tid  = threadIdx.x;
    const int wid  = tid >> 5;
    const int lane = tid & 31;

    __shared__ int   seg_list[8][Kk];
    __shared__ int   seg_cnt[8];
    __shared__ int   idx_s[Kk];
    __shared__ float g_s[3][Kk];
    __shared__ float f_s[Kk][Cc + 1];  // +1 pad: conflict-free transposed read

    // Query point
    const float qx = new_xyz[(b * 3 + 0) * Mm + m];
    const float qy = new_xyz[(b * 3 + 1) * Mm + m];
    const float qz = new_xyz[(b * 3 + 2) * Mm + m];
    const float m2 = __fadd_rn(__fadd_rn(__fmul_rn(qx, qx), __fmul_rn(qy, qy)),
                               __fmul_rn(qz, qz));

    const float* __restrict__ px = xyz + (b * 3 + 0) * Nn;
    const float* __restrict__ py = xyz + (b * 3 + 1) * Nn;
    const float* __restrict__ pz = xyz + (b * 3 + 2) * Nn;
    const float* __restrict__ pn2 = g_n2 + b * Nn;

    // --- Ball query: each warp scans an ascending disjoint segment of 1024 ---
    const int seg_base = wid * (Nn / 8);
    int cnt = 0;
    #pragma unroll 1
    for (int it = 0; it < (Nn / 8) / 32; ++it) {
        const int n = seg_base + it * 32 + lane;
        const float x = px[n], y = py[n], z = pz[n];
        const float n2 = pn2[n];
        // GEMM-order fp32 FMA chain (einsum -> batched gemm, ascending k):
        // acc = fma(a2,b2, fma(a1,b1, a0*b0))
        const float dot = __fmaf_rn(qz, z, __fmaf_rn(qy, y, __fmul_rn(qx, x)));
        const float d2  = __fsub_rn(__fadd_rn(m2, n2), __fmul_rn(2.0f, dot));
        const bool  in  = d2 < 0.01f;   // float32(0.1*0.1) == 0.01f
        const unsigned mask = __ballot_sync(0xffffffffu, in);
        if (in) {
            const int pos = cnt + __popc(mask & ((1u << lane) - 1u));
            if (pos < Kk) seg_list[wid][pos] = n;
        }
        cnt += __popc(mask);
        if (cnt >= Kk) break;           // uniform across warp
    }
    if (lane == 0) seg_cnt[wid] = (cnt < Kk) ? cnt : Kk;
    __syncthreads();

    // --- Ordered merge: segments are ascending, so concat-truncate is exact ---
    if (tid == 0) {
        int total = 0;
        #pragma unroll 1
        for (int s = 0; s < 8 && total < Kk; ++s) {
            const int c = seg_cnt[s];
            for (int i = 0; i < c && total < Kk; ++i)
                idx_s[total++] = seg_list[s][i];
        }
        const int first = (total > 0) ? idx_s[0] : 0;
        for (; total < Kk; ++total) idx_s[total] = first;
    }
    __syncthreads();

    // --- group_xyz into smem ---
    if (tid < 96) {
        const int axis = tid >> 5, j = tid & 31;
        const int n = idx_s[j];
        const float p = xyz[(b * 3 + axis) * Nn + n];
        const float q = new_xyz[(b * 3 + axis) * Mm + m];
        g_s[axis][j] = __fsub_rn(p, q);
    }

    // --- stage features: contiguous 256B per neighbor from transposed layout ---
    #pragma unroll
    for (int l = tid; l < Kk * Cc; l += 256) {
        const int j = l >> 6, c = l & 63;
        f_s[j][c] = g_feat_t[((size_t)(b * Nn + idx_s[j])) * Cc + c];
    }
    __syncthreads();

    // --- write group_feature (B, 67, M, K): coalesced over j ---
    #pragma unroll
    for (int o = tid; o < 67 * Kk; o += 256) {
        const int c = o >> 5, j = o & 31;
        const float v = (c < Cc) ? f_s[j][c] : g_s[c - Cc][j];
        out[(((size_t)(b * 67 + c)) * Mm + m) * Kk + j] = v;
    }

    // --- write group_xyz (B, 3, M, K) appended after group_feature ---
    const size_t GX = (size_t)Bb * 67 * Mm * Kk;
    if (tid < 96) {
        const int c = tid >> 5, j = tid & 31;
        out[GX + (((size_t)(b * 3 + c)) * Mm + m) * Kk + j] = g_s[c][j];
    }
}

// ---------------------------------------------------------------------------
extern "C" void kernel_launch(void* const* d_in, const int* in_sizes, int n_in,
                              void* d_out, int out_size) {
    const float* new_xyz = (const float*)d_in[0];   // (8, 3, 2048)
    const float* xyz     = (const float*)d_in[1];   // (8, 3, 8192)
    const float* feat    = (const float*)d_in[2];   // (8, 64, 8192)
    // d_in[3] = use_xyz (always 1 for this dataset; output shape fixes it)
    float* out = (float*)d_out;

    transpose_kernel<<<dim3(Nn / 32, Cc / 32, Bb), dim3(32, 8)>>>(feat);
    n2_kernel<<<(Bb * Nn + 255) / 256, 256>>>(xyz);
    group_kernel<<<Bb * Mm, 256>>>(new_xyz, xyz, out);
}

// round 3
// speedup vs baseline: 1.1034x; 1.1034x over previous
#include <cuda_runtime.h>
#include <cuda_bf16.h>

// Problem constants (fixed by dataset)
constexpr int Bb = 8;
constexpr int Nn = 8192;
constexpr int Mm = 2048;
constexpr int Cc = 64;
constexpr int Kk = 32;
constexpr int Qq = 16;   // queries per block (amortizes point loads 16x)

// Scratch: transposed feature (B,N,C), packed points (x,y,z,n2)
__device__ float  g_feat_t[Bb * Nn * Cc];   // 16.8 MB
__device__ float4 g_pts[Bb * Nn];           // 512 KB

// ---------------------------------------------------------------------------
// Kernel 1: transpose feature (B,C,N) -> (B,N,C)
// ---------------------------------------------------------------------------
__global__ void transpose_kernel(const float* __restrict__ feat) {
    __shared__ float tile[32][33];
    int b  = blockIdx.z;
    int n0 = blockIdx.x * 32;
    int c0 = blockIdx.y * 32;
    for (int i = threadIdx.y; i < 32; i += 8) {
        tile[i][threadIdx.x] = feat[((size_t)(b * Cc + c0 + i)) * Nn + n0 + threadIdx.x];
    }
    __syncthreads();
    for (int i = threadIdx.y; i < 32; i += 8) {
        g_feat_t[((size_t)(b * Nn + n0 + i)) * Cc + c0 + threadIdx.x] = tile[threadIdx.x][i];
    }
}

// ---------------------------------------------------------------------------
// Kernel 2: pack points as float4(x, y, z, n2); n2 in reference rounding order
// ---------------------------------------------------------------------------
__global__ void prep_kernel(const float* __restrict__ xyz) {
    int t = blockIdx.x * blockDim.x + threadIdx.x;   // 0 .. B*N-1
    if (t >= Bb * Nn) return;
    int b = t >> 13;            // / 8192
    int n = t & (Nn - 1);
    float x = xyz[(b * 3 + 0) * Nn + n];
    float y = xyz[(b * 3 + 1) * Nn + n];
    float z = xyz[(b * 3 + 2) * Nn + n];
    float n2 = __fadd_rn(__fadd_rn(__fmul_rn(x, x), __fmul_rn(y, y)), __fmul_rn(z, z));
    g_pts[t] = make_float4(x, y, z, n2);
}

// ---------------------------------------------------------------------------
// Kernel 3: fused ball-query + grouping. One block (256 thr) per (b, 16 queries).
// Each warp scans a contiguous ascending 1024-point segment (points in regs),
// testing against all 16 queries (smem float4 broadcast).
// ---------------------------------------------------------------------------
__global__ __launch_bounds__(256) void group_kernel(
    const float* __restrict__ new_xyz,
    float* __restrict__ out)
{
    const int b      = blockIdx.y;
    const int m_base = blockIdx.x * Qq;
    const int tid    = threadIdx.x;
    const int wid    = tid >> 5;
    const int lane   = tid & 31;

    __shared__ float4 q_s[Qq];                 // (qx, qy, qz, m2)
    __shared__ int    seg_list[Qq][8][Kk];
    __shared__ int    seg_cnt[Qq][8];
    __shared__ int    idx_s[Qq][Kk];
    __shared__ float  g_s[3][Kk];
    __shared__ float  f_s[Kk][Cc + 1];         // +1 pad: conflict-free transposed read

    // Load query data (reference rounding for m2)
    if (tid < Qq) {
        const int m = m_base + tid;
        const float qx = new_xyz[(b * 3 + 0) * Mm + m];
        const float qy = new_xyz[(b * 3 + 1) * Mm + m];
        const float qz = new_xyz[(b * 3 + 2) * Mm + m];
        const float m2 = __fadd_rn(__fadd_rn(__fmul_rn(qx, qx), __fmul_rn(qy, qy)),
                                   __fmul_rn(qz, qz));
        q_s[tid] = make_float4(qx, qy, qz, m2);
    }
    __syncthreads();

    const float4* __restrict__ pts = g_pts + b * Nn;

    // --- Scan: warp w covers ascending segment [w*1024, (w+1)*1024) ---
    int cnt[Qq];
    #pragma unroll
    for (int q = 0; q < Qq; ++q) cnt[q] = 0;

    const int seg_base = wid * (Nn / 8);
    const unsigned lmask_lt = (1u << lane) - 1u;

    #pragma unroll 1
    for (int it = 0; it < (Nn / 8) / 32; ++it) {
        const int n = seg_base + it * 32 + lane;
        const float4 p = pts[n];
        #pragma unroll
        for (int q = 0; q < Qq; ++q) {
            const float4 Qd = q_s[q];   // LDS.128 broadcast
            // bit-identical to the passing R2 arithmetic:
            const float dot = __fmaf_rn(Qd.z, p.z,
                              __fmaf_rn(Qd.y, p.y, __fmul_rn(Qd.x, p.x)));
            const float d2  = __fsub_rn(__fadd_rn(Qd.w, p.w), __fmul_rn(2.0f, dot));
            const bool  in  = d2 < 0.01f;
            const unsigned mask = __ballot_sync(0xffffffffu, in);
            if (in) {
                const int pos = cnt[q] + __popc(mask & lmask_lt);
                if (pos < Kk) seg_list[q][wid][pos] = n;
            }
            cnt[q] += __popc(mask);
        }
    }
    if (lane == 0) {
        #pragma unroll
        for (int q = 0; q < Qq; ++q)
            seg_cnt[q][wid] = (cnt[q] < Kk) ? cnt[q] : Kk;
    }
    __syncthreads();

    // --- Ordered merge: one thread per query (segments ascending & disjoint) ---
    if (tid < Qq) {
        int total = 0;
        #pragma unroll 1
        for (int s = 0; s < 8 && total < Kk; ++s) {
            const int c = seg_cnt[tid][s];
            for (int i = 0; i < c && total < Kk; ++i)
                idx_s[tid][total++] = seg_list[tid][s][i];
        }
        const int first = (total > 0) ? idx_s[tid][0] : 0;
        for (; total < Kk; ++total) idx_s[tid][total] = first;
    }
    __syncthreads();

    // --- Output phase, one query at a time ---
    const float* __restrict__ ft = g_feat_t + (size_t)b * Nn * Cc;
    const size_t GX = (size_t)Bb * 67 * Mm * Kk;

    #pragma unroll 1
    for (int q = 0; q < Qq; ++q) {
        const int m = m_base + q;

        // group_xyz into smem
        if (tid < Kk) {
            const float4 p  = pts[idx_s[q][tid]];
            const float4 Qd = q_s[q];
            g_s[0][tid] = __fsub_rn(p.x, Qd.x);
            g_s[1][tid] = __fsub_rn(p.y, Qd.y);
            g_s[2][tid] = __fsub_rn(p.z, Qd.z);
        }

        // stage features: contiguous 256B per neighbor from transposed layout
        #pragma unroll
        for (int l = tid; l < Kk * Cc; l += 256) {
            const int j = l >> 6, c = l & 63;
            f_s[j][c] = ft[(size_t)idx_s[q][j] * Cc + c];
        }
        __syncthreads();

        // group_feature (B, 67, M, K): coalesced over j; f_s stride 65 -> no conflicts
        #pragma unroll
        for (int o = tid; o < 67 * Kk; o += 256) {
            const int c = o >> 5, j = o & 31;
            const float v = (c < Cc) ? f_s[j][c] : g_s[c - Cc][j];
            out[(((size_t)(b * 67 + c)) * Mm + m) * Kk + j] = v;
        }

        // group_xyz (B, 3, M, K) appended after group_feature
        if (tid < 96) {
            const int c = tid >> 5, j = tid & 31;
            out[GX + (((size_t)(b * 3 + c)) * Mm + m) * Kk + j] = g_s[c][j];
        }
        __syncthreads();   // before reusing f_s / g_s
    }
}

// ---------------------------------------------------------------------------
extern "C" void kernel_launch(void* const* d_in, const int* in_sizes, int n_in,
                              void* d_out, int out_size) {
    const float* new_xyz = (const float*)d_in[0];   // (8, 3, 2048)
    const float* xyz     = (const float*)d_in[1];   // (8, 3, 8192)
    const float* feat    = (const float*)d_in[2];   // (8, 64, 8192)
    float* out = (float*)d_out;

    prep_kernel<<<(Bb * Nn + 255) / 256, 256>>>(xyz);
    transpose_kernel<<<dim3(Nn / 32, Cc / 32, Bb), dim3(32, 8)>>>(feat);
    group_kernel<<<dim3(Mm / Qq, Bb), 256>>>(new_xyz, out);
}

// round 4
// speedup vs baseline: 1.6184x; 1.4667x over previous
#include <cuda_runtime.h>
#include <cuda_bf16.h>

// Problem constants (fixed by dataset)
constexpr int Bb = 8;
constexpr int Nn = 8192;
constexpr int Mm = 2048;
constexpr int Cc = 64;
constexpr int Kk = 32;

// Spatial grid: 8x8x8 cells of 0.125 (>= radius 0.1 -> 27-cell neighborhood exact)
constexpr int Gg    = 8;
constexpr int CELLS = Gg * Gg * Gg;        // 512
constexpr int BINS  = Bb * CELLS;          // 4096
constexpr int NPTS  = Bb * Nn;             // 65536
constexpr int CAP   = 128;                 // max candidates/query (lambda~34, +16 sigma)
constexpr int SENT  = 0x3FFFFFFF;

// Scratch (__device__ globals: no allocs allowed)
__device__ float  g_feat_t[Bb * Nn * Cc];  // transposed features (B,N,C)
__device__ float4 g_pts[NPTS];             // (x,y,z,n2) original order
__device__ int    g_binid[NPTS];
__device__ int    g_cnt[BINS];
__device__ int    g_cursor[BINS];
__device__ int    g_start[BINS + 1];
__device__ float4 g_spts[NPTS];            // grid-sorted points
__device__ int    g_sidx[NPTS];            // original within-batch index

// ---------------------------------------------------------------------------
__global__ void zero_kernel() {
    int t = blockIdx.x * blockDim.x + threadIdx.x;
    if (t < BINS) { g_cnt[t] = 0; g_cursor[t] = 0; }
}

// pack (x,y,z,n2), compute bin, histogram
__global__ void prep_kernel(const float* __restrict__ xyz) {
    int t = blockIdx.x * blockDim.x + threadIdx.x;
    if (t >= NPTS) return;
    int b = t >> 13;
    int n = t & (Nn - 1);
    float x = xyz[(b * 3 + 0) * Nn + n];
    float y = xyz[(b * 3 + 1) * Nn + n];
    float z = xyz[(b * 3 + 2) * Nn + n];
    float n2 = __fadd_rn(__fadd_rn(__fmul_rn(x, x), __fmul_rn(y, y)), __fmul_rn(z, z));
    g_pts[t] = make_float4(x, y, z, n2);
    int cx = min(Gg - 1, max(0, (int)(x * Gg)));
    int cy = min(Gg - 1, max(0, (int)(y * Gg)));
    int cz = min(Gg - 1, max(0, (int)(z * Gg)));
    int bin = b * CELLS + ((cz * Gg + cy) * Gg + cx);
    g_binid[t] = bin;
    atomicAdd(&g_cnt[bin], 1);
}

// exclusive scan of 4096 bins, one block of 1024 threads (4 bins each)
__global__ void scan_kernel() {
    __shared__ int s[1024];
    int t = threadIdx.x;
    int base = t * 4;
    int v0 = g_cnt[base], v1 = g_cnt[base + 1], v2 = g_cnt[base + 2], v3 = g_cnt[base + 3];
    int sum = v0 + v1 + v2 + v3;
    s[t] = sum;
    __syncthreads();
    for (int off = 1; off < 1024; off <<= 1) {
        int x = (t >= off) ? s[t - off] : 0;
        __syncthreads();
        s[t] += x;
        __syncthreads();
    }
    int excl = s[t] - sum;
    g_start[base]     = excl;
    g_start[base + 1] = excl + v0;
    g_start[base + 2] = excl + v0 + v1;
    g_start[base + 3] = excl + v0 + v1 + v2;
    if (t == 1023) g_start[BINS] = s[1023];
}

__global__ void scatter_kernel() {
    int t = blockIdx.x * blockDim.x + threadIdx.x;
    if (t >= NPTS) return;
    int bin = g_binid[t];
    int pos = g_start[bin] + atomicAdd(&g_cursor[bin], 1);
    g_spts[pos] = g_pts[t];
    g_sidx[pos] = t & (Nn - 1);
}

// feature transpose (B,C,N) -> (B,N,C)
__global__ void transpose_kernel(const float* __restrict__ feat) {
    __shared__ float tile[32][33];
    int b  = blockIdx.z;
    int n0 = blockIdx.x * 32;
    int c0 = blockIdx.y * 32;
    for (int i = threadIdx.y; i < 32; i += 8)
        tile[i][threadIdx.x] = feat[((size_t)(b * Cc + c0 + i)) * Nn + n0 + threadIdx.x];
    __syncthreads();
    for (int i = threadIdx.y; i < 32; i += 8)
        g_feat_t[((size_t)(b * Nn + n0 + i)) * Cc + c0 + threadIdx.x] = tile[threadIdx.x][i];
}

// ---------------------------------------------------------------------------
// Fused query: block = 256 thr = 8 warps = 8 queries. Warp scans its query's
// 27-cell neighborhood (exact test, bit-identical rounding), collects hit
// indices, extracts the 32 smallest, then block does the grouped output.
// ---------------------------------------------------------------------------
__global__ __launch_bounds__(256) void group_kernel(
    const float* __restrict__ new_xyz,
    float* __restrict__ out)
{
    constexpr int QB = 8;                   // queries per block
    const int b      = blockIdx.y;
    const int m_base = blockIdx.x * QB;
    const int tid    = threadIdx.x;
    const int wid    = tid >> 5;
    const int lane   = tid & 31;

    __shared__ float4 q_s[QB];
    __shared__ int    cand[QB][CAP];
    __shared__ int    idx_s[QB][Kk];
    __shared__ float  g_s[3][Kk];
    __shared__ float  f_s[Kk][Cc + 1];

    const int m = m_base + wid;
    const float qx = new_xyz[(b * 3 + 0) * Mm + m];
    const float qy = new_xyz[(b * 3 + 1) * Mm + m];
    const float qz = new_xyz[(b * 3 + 2) * Mm + m];
    const float m2 = __fadd_rn(__fadd_rn(__fmul_rn(qx, qx), __fmul_rn(qy, qy)),
                               __fmul_rn(qz, qz));
    if (lane == 0) q_s[wid] = make_float4(qx, qy, qz, m2);

    // --- candidate scan over 27-cell neighborhood ---
    const int qcx = min(Gg - 1, max(0, (int)(qx * Gg)));
    const int qcy = min(Gg - 1, max(0, (int)(qy * Gg)));
    const int qcz = min(Gg - 1, max(0, (int)(qz * Gg)));
    const int x0 = max(0, qcx - 1), x1 = min(Gg - 1, qcx + 1);
    const int y0 = max(0, qcy - 1), y1 = min(Gg - 1, qcy + 1);
    const int z0 = max(0, qcz - 1), z1 = min(Gg - 1, qcz + 1);
    const unsigned lmask_lt = (1u << lane) - 1u;

    int cand_cnt = 0;
    for (int cz = z0; cz <= z1; ++cz) {
        for (int cy = y0; cy <= y1; ++cy) {
            const int bin0 = b * CELLS + (cz * Gg + cy) * Gg + x0;
            const int s = g_start[bin0];
            const int e = g_start[bin0 + (x1 - x0) + 1];   // x-cells contiguous
            for (int base = s; base < e; base += 32) {
                const int i = base + lane;
                const bool v = i < e;
                bool in = false;
                int pid = 0;
                if (v) {
                    const float4 p = g_spts[i];
                    pid = g_sidx[i];
                    // bit-identical to the passing arithmetic:
                    const float dot = __fmaf_rn(qz, p.z,
                                      __fmaf_rn(qy, p.y, __fmul_rn(qx, p.x)));
                    const float d2  = __fsub_rn(__fadd_rn(m2, p.w), __fmul_rn(2.0f, dot));
                    in = d2 < 0.01f;
                }
                const unsigned mask = __ballot_sync(0xffffffffu, in);
                if (in) {
                    const int pos = cand_cnt + __popc(mask & lmask_lt);
                    if (pos < CAP) cand[wid][pos] = pid;
                }
                cand_cnt += __popc(mask);
            }
        }
    }
    if (cand_cnt > CAP) cand_cnt = CAP;

    // --- select 32 smallest indices (warp min-extraction, 4 regs/lane) ---
    int a[4];
    #pragma unroll
    for (int k = 0; k < 4; ++k) {
        const int p = k * 32 + lane;
        a[k] = (p < cand_cnt) ? cand[wid][p] : SENT;
    }
    {   // sort each lane's 4 ascending
        int lo, hi;
        lo = min(a[0], a[1]); hi = max(a[0], a[1]); a[0] = lo; a[1] = hi;
        lo = min(a[2], a[3]); hi = max(a[2], a[3]); a[2] = lo; a[3] = hi;
        lo = min(a[0], a[2]); hi = max(a[0], a[2]); a[0] = lo; a[2] = hi;
        lo = min(a[1], a[3]); hi = max(a[1], a[3]); a[1] = lo; a[3] = hi;
        lo = min(a[1], a[2]); hi = max(a[1], a[2]); a[1] = lo; a[2] = hi;
    }
    #pragma unroll 1
    for (int r = 0; r < Kk; ++r) {
        int mv = a[0];
        #pragma unroll
        for (int off = 16; off >= 1; off >>= 1)
            mv = min(mv, __shfl_xor_sync(0xffffffffu, mv, off));
        const unsigned tie = __ballot_sync(0xffffffffu, a[0] == mv);
        if (lane == (int)(__ffs(tie) - 1)) {
            a[0] = a[1]; a[1] = a[2]; a[2] = a[3]; a[3] = SENT;
        }
        if (lane == 0) idx_s[wid][r] = mv;
    }
    __syncwarp();
    {   // pad: sentinel -> first (or 0 if empty); reference semantics
        int v = idx_s[wid][lane];
        int first = idx_s[wid][0];
        first = (first >= Nn) ? 0 : first;
        v = (v >= Nn) ? first : v;
        __syncwarp();
        idx_s[wid][lane] = v;
    }
    __syncthreads();

    // --- output phase, one query at a time ---
    const float4* __restrict__ pts = g_pts + b * Nn;
    const float*  __restrict__ ft  = g_feat_t + (size_t)b * Nn * Cc;
    const size_t GX = (size_t)Bb * 67 * Mm * Kk;

    #pragma unroll 1
    for (int q = 0; q < QB; ++q) {
        const int mq = m_base + q;

        if (tid < Kk) {
            const float4 p  = pts[idx_s[q][tid]];
            const float4 Qd = q_s[q];
            g_s[0][tid] = __fsub_rn(p.x, Qd.x);
            g_s[1][tid] = __fsub_rn(p.y, Qd.y);
            g_s[2][tid] = __fsub_rn(p.z, Qd.z);
        }
        // stage features: contiguous 256B per neighbor
        #pragma unroll
        for (int l = tid; l < Kk * Cc; l += 256) {
            const int j = l >> 6, c = l & 63;
            f_s[j][c] = ft[(size_t)idx_s[q][j] * Cc + c];
        }
        __syncthreads();

        // group_feature (B, 67, M, K): coalesced over j
        #pragma unroll
        for (int o = tid; o < 67 * Kk; o += 256) {
            const int c = o >> 5, j = o & 31;
            const float v = (c < Cc) ? f_s[j][c] : g_s[c - Cc][j];
            out[(((size_t)(b * 67 + c)) * Mm + mq) * Kk + j] = v;
        }
        // group_xyz (B, 3, M, K) appended
        if (tid < 96) {
            const int c = tid >> 5, j = tid & 31;
            out[GX + (((size_t)(b * 3 + c)) * Mm + mq) * Kk + j] = g_s[c][j];
        }
        __syncthreads();
    }
}

// ---------------------------------------------------------------------------
extern "C" void kernel_launch(void* const* d_in, const int* in_sizes, int n_in,
                              void* d_out, int out_size) {
    const float* new_xyz = (const float*)d_in[0];   // (8, 3, 2048)
    const float* xyz     = (const float*)d_in[1];   // (8, 3, 8192)
    const float* feat    = (const float*)d_in[2];   // (8, 64, 8192)
    float* out = (float*)d_out;

    zero_kernel<<<(BINS + 255) / 256, 256>>>();
    prep_kernel<<<(NPTS + 255) / 256, 256>>>(xyz);
    transpose_kernel<<<dim3(Nn / 32, Cc / 32, Bb), dim3(32, 8)>>>(feat);
    scan_kernel<<<1, 1024>>>();
    scatter_kernel<<<(NPTS + 255) / 256, 256>>>();
    group_kernel<<<dim3(Mm / 8, Bb), 256>>>(new_xyz, out);
}

// round 5
// speedup vs baseline: 2.4880x; 1.5373x over previous
#include <cuda_runtime.h>
#include <cuda_bf16.h>

// Problem constants (fixed by dataset)
constexpr int Bb = 8;
constexpr int Nn = 8192;
constexpr int Mm = 2048;
constexpr int Cc = 64;
constexpr int Kk = 32;

// Spatial grid: 8x8x8 cells of 0.125 (>= radius 0.1 -> 27-cell neighborhood exact)
constexpr int Gg    = 8;
constexpr int CELLS = Gg * Gg * Gg;        // 512
constexpr int BINS  = Bb * CELLS;          // 4096
constexpr int NPTS  = Bb * Nn;             // 65536
constexpr int CAP   = 128;                 // max candidates/query (lambda~34)
constexpr int SENT  = 0x3FFFFFFF;

// Scratch (__device__ globals: no allocs allowed)
__device__ float  g_feat_t[Bb * Nn * Cc];  // transposed features (B,N,C)
__device__ float4 g_pts[NPTS];             // (x,y,z,n2) original order
__device__ int    g_binid[NPTS];
__device__ int    g_cnt[BINS];
__device__ int    g_cursor[BINS];
__device__ int    g_start[BINS + 1];
__device__ float4 g_spts[NPTS];            // grid-sorted points
__device__ int    g_sidx[NPTS];            // original within-batch index
__device__ int    g_idx[Bb * Mm * Kk];     // selected neighbor indices

// ---------------------------------------------------------------------------
__global__ void zero_kernel() {
    int t = blockIdx.x * blockDim.x + threadIdx.x;
    if (t < BINS) { g_cnt[t] = 0; g_cursor[t] = 0; }
}

// pack (x,y,z,n2), compute bin, histogram
__global__ void prep_kernel(const float* __restrict__ xyz) {
    int t = blockIdx.x * blockDim.x + threadIdx.x;
    if (t >= NPTS) return;
    int b = t >> 13;
    int n = t & (Nn - 1);
    float x = xyz[(b * 3 + 0) * Nn + n];
    float y = xyz[(b * 3 + 1) * Nn + n];
    float z = xyz[(b * 3 + 2) * Nn + n];
    float n2 = __fadd_rn(__fadd_rn(__fmul_rn(x, x), __fmul_rn(y, y)), __fmul_rn(z, z));
    g_pts[t] = make_float4(x, y, z, n2);
    int cx = min(Gg - 1, max(0, (int)(x * Gg)));
    int cy = min(Gg - 1, max(0, (int)(y * Gg)));
    int cz = min(Gg - 1, max(0, (int)(z * Gg)));
    int bin = b * CELLS + ((cz * Gg + cy) * Gg + cx);
    g_binid[t] = bin;
    atomicAdd(&g_cnt[bin], 1);
}

// exclusive scan of 4096 bins: 1024 threads, shuffle-based (3 barriers)
__global__ void scan_kernel() {
    __shared__ int wsum[32];
    const int t = threadIdx.x, lane = t & 31, w = t >> 5;
    const int base = t * 4;
    const int v0 = g_cnt[base], v1 = g_cnt[base + 1], v2 = g_cnt[base + 2], v3 = g_cnt[base + 3];
    const int sum = v0 + v1 + v2 + v3;
    int incl = sum;
    #pragma unroll
    for (int off = 1; off < 32; off <<= 1) {
        int x = __shfl_up_sync(0xffffffffu, incl, off);
        if (lane >= off) incl += x;
    }
    if (lane == 31) wsum[w] = incl;
    __syncthreads();
    if (w == 0) {
        int s = wsum[lane];
        int si = s;
        #pragma unroll
        for (int off = 1; off < 32; off <<= 1) {
            int x = __shfl_up_sync(0xffffffffu, si, off);
            if (lane >= off) si += x;
        }
        wsum[lane] = si - s;   // exclusive warp offsets
    }
    __syncthreads();
    const int excl = wsum[w] + incl - sum;
    g_start[base]     = excl;
    g_start[base + 1] = excl + v0;
    g_start[base + 2] = excl + v0 + v1;
    g_start[base + 3] = excl + v0 + v1 + v2;
    if (t == 1023) g_start[BINS] = wsum[31] + incl;
}

__global__ void scatter_kernel() {
    int t = blockIdx.x * blockDim.x + threadIdx.x;
    if (t >= NPTS) return;
    int bin = g_binid[t];
    int pos = g_start[bin] + atomicAdd(&g_cursor[bin], 1);
    g_spts[pos] = g_pts[t];
    g_sidx[pos] = t & (Nn - 1);
}

// feature transpose (B,C,N) -> (B,N,C), float4 both sides, 64x64 tiles
__global__ __launch_bounds__(256) void transpose_kernel(const float* __restrict__ feat) {
    __shared__ float tile[64][65];
    const int b  = blockIdx.z;
    const int n0 = blockIdx.x * 64;
    const int t  = threadIdx.x;
    const int j4 = (t & 15) * 4;
    // load 64 channels x 64 points
    #pragma unroll
    for (int p = 0; p < 4; ++p) {
        const int row = p * 16 + (t >> 4);     // channel
        const float4 v = *(const float4*)&feat[((size_t)(b * Cc + row)) * Nn + n0 + j4];
        tile[row][j4 + 0] = v.x; tile[row][j4 + 1] = v.y;
        tile[row][j4 + 2] = v.z; tile[row][j4 + 3] = v.w;
    }
    __syncthreads();
    // write 64 points x 64 channels (256B contiguous per point)
    #pragma unroll
    for (int p = 0; p < 4; ++p) {
        const int r = p * 16 + (t >> 4);       // point within tile
        float4 v;
        v.x = tile[j4 + 0][r]; v.y = tile[j4 + 1][r];
        v.z = tile[j4 + 2][r]; v.w = tile[j4 + 3][r];
        *(float4*)&g_feat_t[((size_t)(b * Nn + n0 + r)) * Cc + j4] = v;
    }
}

// ---------------------------------------------------------------------------
// Select: 8 warps/block, warp <-> query. Grid-pruned exact ball query,
// 32 smallest indices ascending via REDUX-min extraction.
// ---------------------------------------------------------------------------
__global__ __launch_bounds__(256) void select_kernel(const float* __restrict__ new_xyz)
{
    const int b    = blockIdx.y;
    const int m    = blockIdx.x * 8 + (threadIdx.x >> 5);
    const int wid  = threadIdx.x >> 5;
    const int lane = threadIdx.x & 31;

    __shared__ int cand[8][CAP];
    __shared__ int idx_w[8][Kk];

    const float qx = new_xyz[(b * 3 + 0) * Mm + m];
    const float qy = new_xyz[(b * 3 + 1) * Mm + m];
    const float qz = new_xyz[(b * 3 + 2) * Mm + m];
    const float m2 = __fadd_rn(__fadd_rn(__fmul_rn(qx, qx), __fmul_rn(qy, qy)),
                               __fmul_rn(qz, qz));

    const int qcx = min(Gg - 1, max(0, (int)(qx * Gg)));
    const int qcy = min(Gg - 1, max(0, (int)(qy * Gg)));
    const int qcz = min(Gg - 1, max(0, (int)(qz * Gg)));
    const int x0 = max(0, qcx - 1), x1 = min(Gg - 1, qcx + 1);
    const int y0 = max(0, qcy - 1), y1 = min(Gg - 1, qcy + 1);
    const int z0 = max(0, qcz - 1), z1 = min(Gg - 1, qcz + 1);
    const unsigned lmask_lt = (1u << lane) - 1u;

    int cand_cnt = 0;
    for (int cz = z0; cz <= z1; ++cz) {
        for (int cy = y0; cy <= y1; ++cy) {
            const int bin0 = b * CELLS + (cz * Gg + cy) * Gg + x0;
            const int s = g_start[bin0];
            const int e = g_start[bin0 + (x1 - x0) + 1];   // x-cells contiguous
            for (int base = s; base < e; base += 32) {
                const int i = base + lane;
                bool in = false;
                int pid = 0;
                if (i < e) {
                    const float4 p = g_spts[i];
                    pid = g_sidx[i];
                    // bit-identical to the passing arithmetic:
                    const float dot = __fmaf_rn(qz, p.z,
                                      __fmaf_rn(qy, p.y, __fmul_rn(qx, p.x)));
                    const float d2  = __fsub_rn(__fadd_rn(m2, p.w), __fmul_rn(2.0f, dot));
                    in = d2 < 0.01f;
                }
                const unsigned mask = __ballot_sync(0xffffffffu, in);
                if (in) {
                    const int pos = cand_cnt + __popc(mask & lmask_lt);
                    if (pos < CAP) cand[wid][pos] = pid;
                }
                cand_cnt += __popc(mask);
            }
        }
    }
    if (cand_cnt > CAP) cand_cnt = CAP;

    // 4 items per lane, lane-local ascending sort
    int a[4];
    #pragma unroll
    for (int k = 0; k < 4; ++k) {
        const int p = k * 32 + lane;
        a[k] = (p < cand_cnt) ? cand[wid][p] : SENT;
    }
    {
        int lo, hi;
        lo = min(a[0], a[1]); hi = max(a[0], a[1]); a[0] = lo; a[1] = hi;
        lo = min(a[2], a[3]); hi = max(a[2], a[3]); a[2] = lo; a[3] = hi;
        lo = min(a[0], a[2]); hi = max(a[0], a[2]); a[0] = lo; a[2] = hi;
        lo = min(a[1], a[3]); hi = max(a[1], a[3]); a[1] = lo; a[3] = hi;
        lo = min(a[1], a[2]); hi = max(a[1], a[2]); a[1] = lo; a[2] = hi;
    }
    // 32 rounds of REDUX-min extraction -> ascending indices
    #pragma unroll 1
    for (int r = 0; r < Kk; ++r) {
        const int mv = __reduce_min_sync(0xffffffffu, a[0]);
        const unsigned tie = __ballot_sync(0xffffffffu, a[0] == mv);
        if (lane == (int)(__ffs(tie) - 1)) {
            a[0] = a[1]; a[1] = a[2]; a[2] = a[3]; a[3] = SENT;
        }
        if (lane == 0) idx_w[wid][r] = mv;
    }
    __syncwarp();
    // pad: sentinel -> first (or 0 if empty)
    int v = idx_w[wid][lane];
    int first = idx_w[wid][0];
    first = (first >= Nn) ? 0 : first;
    v = (v >= Nn) ? first : v;
    g_idx[((size_t)b * Mm + m) * Kk + lane] = v;
}

// ---------------------------------------------------------------------------
// Output: 2 queries per 256-thread block, processed concurrently.
// ---------------------------------------------------------------------------
__global__ __launch_bounds__(256) void output_kernel(
    const float* __restrict__ new_xyz,
    float* __restrict__ out)
{
    const int b   = blockIdx.y;
    const int m0  = blockIdx.x * 2;
    const int tid = threadIdx.x;

    __shared__ int   idx_s[2][Kk];
    __shared__ float g_s[2][3][Kk];
    __shared__ float f_s[2][Kk][Cc + 1];

    if (tid < 2 * Kk) {
        idx_s[tid >> 5][tid & 31] = g_idx[((size_t)b * Mm + m0 + (tid >> 5)) * Kk + (tid & 31)];
    }
    __syncthreads();

    const float4* __restrict__ pts = g_pts + b * Nn;
    const float*  __restrict__ ft  = g_feat_t + (size_t)b * Nn * Cc;

    if (tid < 2 * Kk) {
        const int q = tid >> 5, j = tid & 31;
        const float4 p = pts[idx_s[q][j]];
        g_s[q][0][j] = __fsub_rn(p.x, new_xyz[(b * 3 + 0) * Mm + m0 + q]);
        g_s[q][1][j] = __fsub_rn(p.y, new_xyz[(b * 3 + 1) * Mm + m0 + q]);
        g_s[q][2][j] = __fsub_rn(p.z, new_xyz[(b * 3 + 2) * Mm + m0 + q]);
    }

    // stage features: contiguous 256B per neighbor
    #pragma unroll
    for (int l = tid; l < 2 * Kk * Cc; l += 256) {
        const int q = l >> 11, j = (l >> 6) & 31, c = l & 63;
        f_s[q][j][c] = ft[(size_t)idx_s[q][j] * Cc + c];
    }
    __syncthreads();

    // group_feature (B, 67, M, K): (c, q, j) flattened -> 256B contiguous per c
    #pragma unroll
    for (int o = tid; o < 67 * 2 * Kk; o += 256) {
        const int c = o >> 6, q = (o >> 5) & 1, j = o & 31;
        const float v = (c < Cc) ? f_s[q][j][c] : g_s[q][c - Cc][j];
        out[(((size_t)(b * 67 + c)) * Mm + m0 + q) * Kk + j] = v;
    }
    // group_xyz (B, 3, M, K) appended
    const size_t GX = (size_t)Bb * 67 * Mm * Kk;
    if (tid < 2 * 3 * Kk) {
        const int axis = tid >> 6, q = (tid >> 5) & 1, j = tid & 31;
        out[GX + (((size_t)(b * 3 + axis)) * Mm + m0 + q) * Kk + j] = g_s[q][axis][j];
    }
}

// ---------------------------------------------------------------------------
extern "C" void kernel_launch(void* const* d_in, const int* in_sizes, int n_in,
                              void* d_out, int out_size) {
    const float* new_xyz = (const float*)d_in[0];   // (8, 3, 2048)
    const float* xyz     = (const float*)d_in[1];   // (8, 3, 8192)
    const float* feat    = (const float*)d_in[2];   // (8, 64, 8192)
    float* out = (float*)d_out;

    zero_kernel<<<(BINS + 255) / 256, 256>>>();
    prep_kernel<<<(NPTS + 255) / 256, 256>>>(xyz);
    transpose_kernel<<<dim3(Nn / 64, 1, Bb), 256>>>(feat);
    scan_kernel<<<1, 1024>>>();
    scatter_kernel<<<(NPTS + 255) / 256, 256>>>();
    select_kernel<<<dim3(Mm / 8, Bb), 256>>>(new_xyz);
    output_kernel<<<dim3(Mm / 2, Bb), 256>>>(new_xyz, out);
}

// round 6
// speedup vs baseline: 2.8502x; 1.1456x over previous
#include <cuda_runtime.h>
#include <cuda_bf16.h>

// Problem constants (fixed by dataset)
constexpr int Bb = 8;
constexpr int Nn = 8192;
constexpr int Mm = 2048;
constexpr int Cc = 64;
constexpr int Kk = 32;

// Spatial grid: 8x8x8 cells of 0.125 (>= radius 0.1 -> 27-cell neighborhood exact)
constexpr int Gg    = 8;
constexpr int CELLS = Gg * Gg * Gg;        // 512
constexpr int BINS  = Bb * CELLS;          // 4096
constexpr int NPTS  = Bb * Nn;             // 65536
constexpr int CAP   = 128;                 // max candidates/query (lambda~34)
constexpr int SENT  = 0x3FFFFFFF;

// Scratch (__device__ globals: no allocs allowed)
__device__ float  g_feat_t[Bb * Nn * Cc];            // transposed features (B,N,C)
__device__ float4 g_pts[NPTS];                       // (x,y,z,n2) original order
__device__ int    g_binid[NPTS];
__device__ __align__(16) int g_cnt[BINS];
__device__ int    g_cursor[BINS];
__device__ __align__(16) int g_start[BINS + 4];      // padded for int4 stores
__device__ float4 g_spts[NPTS];                      // grid-sorted points
__device__ int    g_sidx[NPTS];                      // original within-batch index

// ---------------------------------------------------------------------------
__global__ void zero_kernel() {
    int t = blockIdx.x * blockDim.x + threadIdx.x;
    if (t < BINS) { g_cnt[t] = 0; g_cursor[t] = 0; }
}

// ---------------------------------------------------------------------------
// Fused: blocks [0, 1024) transpose feature (B,C,N)->(B,N,C) in 64x64 tiles;
// blocks [1024, 1280) pack points (x,y,z,n2) + histogram bins.
// ---------------------------------------------------------------------------
constexpr int TP_BLOCKS = (Nn / 64) * Bb;   // 1024

__global__ __launch_bounds__(256) void prep_transpose_kernel(
    const float* __restrict__ xyz, const float* __restrict__ feat)
{
    __shared__ float tile[64][65];
    const int t = threadIdx.x;

    if (blockIdx.x < TP_BLOCKS) {
        const int b  = blockIdx.x >> 7;
        const int n0 = (blockIdx.x & 127) * 64;
        const int j4 = (t & 15) * 4;
        #pragma unroll
        for (int p = 0; p < 4; ++p) {
            const int row = p * 16 + (t >> 4);     // channel
            const float4 v = *(const float4*)&feat[((size_t)(b * Cc + row)) * Nn + n0 + j4];
            tile[row][j4 + 0] = v.x; tile[row][j4 + 1] = v.y;
            tile[row][j4 + 2] = v.z; tile[row][j4 + 3] = v.w;
        }
        __syncthreads();
        #pragma unroll
        for (int p = 0; p < 4; ++p) {
            const int r = p * 16 + (t >> 4);       // point within tile
            float4 v;
            v.x = tile[j4 + 0][r]; v.y = tile[j4 + 1][r];
            v.z = tile[j4 + 2][r]; v.w = tile[j4 + 3][r];
            *(float4*)&g_feat_t[((size_t)(b * Nn + n0 + r)) * Cc + j4] = v;
        }
    } else {
        const int i = (blockIdx.x - TP_BLOCKS) * 256 + t;   // 0 .. NPTS-1
        const int b = i >> 13;
        const int n = i & (Nn - 1);
        const float x = xyz[(b * 3 + 0) * Nn + n];
        const float y = xyz[(b * 3 + 1) * Nn + n];
        const float z = xyz[(b * 3 + 2) * Nn + n];
        const float n2 = __fadd_rn(__fadd_rn(__fmul_rn(x, x), __fmul_rn(y, y)),
                                   __fmul_rn(z, z));
        g_pts[i] = make_float4(x, y, z, n2);
        const int cx = min(Gg - 1, max(0, (int)(x * Gg)));
        const int cy = min(Gg - 1, max(0, (int)(y * Gg)));
        const int cz = min(Gg - 1, max(0, (int)(z * Gg)));
        const int bin = b * CELLS + ((cz * Gg + cy) * Gg + cx);
        g_binid[i] = bin;
        atomicAdd(&g_cnt[bin], 1);
    }
}

// ---------------------------------------------------------------------------
// Exclusive scan of 4096 bins: 256 threads x 16 bins, int4 loads/stores.
// ---------------------------------------------------------------------------
__global__ __launch_bounds__(256) void scan_kernel() {
    __shared__ int wsum[8];
    const int t = threadIdx.x, lane = t & 31, w = t >> 5;
    int vals[16];
    #pragma unroll
    for (int k = 0; k < 4; ++k) {
        const int4 v = *(const int4*)&g_cnt[t * 16 + k * 4];
        vals[k * 4 + 0] = v.x; vals[k * 4 + 1] = v.y;
        vals[k * 4 + 2] = v.z; vals[k * 4 + 3] = v.w;
    }
    int sum = 0;
    int pre[16];
    #pragma unroll
    for (int k = 0; k < 16; ++k) { pre[k] = sum; sum += vals[k]; }
    int incl = sum;
    #pragma unroll
    for (int off = 1; off < 32; off <<= 1) {
        const int x = __shfl_up_sync(0xffffffffu, incl, off);
        if (lane >= off) incl += x;
    }
    if (lane == 31) wsum[w] = incl;
    __syncthreads();
    if (t == 0) {
        int acc = 0;
        #pragma unroll
        for (int i = 0; i < 8; ++i) { const int x = wsum[i]; wsum[i] = acc; acc += x; }
        g_start[BINS] = acc;
    }
    __syncthreads();
    const int excl = wsum[w] + incl - sum;
    #pragma unroll
    for (int k = 0; k < 4; ++k) {
        int4 o;
        o.x = excl + pre[k * 4 + 0]; o.y = excl + pre[k * 4 + 1];
        o.z = excl + pre[k * 4 + 2]; o.w = excl + pre[k * 4 + 3];
        *(int4*)&g_start[t * 16 + k * 4] = o;
    }
}

__global__ void scatter_kernel() {
    int t = blockIdx.x * blockDim.x + threadIdx.x;
    if (t >= NPTS) return;
    int bin = g_binid[t];
    int pos = g_start[bin] + atomicAdd(&g_cursor[bin], 1);
    g_spts[pos] = g_pts[t];
    g_sidx[pos] = t & (Nn - 1);
}

// ---------------------------------------------------------------------------
// Fused select + output. Block = 256 thr = 8 warps = 8 queries.
// Select: warp-per-query grid-pruned exact ball query + REDUX-min extraction.
// Output: 4 pair-iterations, 2 queries concurrently, vectorized staging.
// ---------------------------------------------------------------------------
__global__ __launch_bounds__(256) void group_kernel(
    const float* __restrict__ new_xyz,
    float* __restrict__ out)
{
    const int b      = blockIdx.y;
    const int m_base = blockIdx.x * 8;
    const int tid    = threadIdx.x;
    const int wid    = tid >> 5;
    const int lane   = tid & 31;

    __shared__ int    cand[8][CAP];
    __shared__ int    idx_sh[8][Kk];
    __shared__ float4 q_sh[8];
    __shared__ float  g_s[2][3][Kk];
    __shared__ float  f_s[2][Kk][Cc + 1];

    // ---- SELECT (warp <-> query) ----
    const int m = m_base + wid;
    const float qx = new_xyz[(b * 3 + 0) * Mm + m];
    const float qy = new_xyz[(b * 3 + 1) * Mm + m];
    const float qz = new_xyz[(b * 3 + 2) * Mm + m];
    const float m2 = __fadd_rn(__fadd_rn(__fmul_rn(qx, qx), __fmul_rn(qy, qy)),
                               __fmul_rn(qz, qz));
    if (lane == 0) q_sh[wid] = make_float4(qx, qy, qz, m2);

    const int qcx = min(Gg - 1, max(0, (int)(qx * Gg)));
    const int qcy = min(Gg - 1, max(0, (int)(qy * Gg)));
    const int qcz = min(Gg - 1, max(0, (int)(qz * Gg)));
    const int x0 = max(0, qcx - 1), x1 = min(Gg - 1, qcx + 1);
    const int y0 = max(0, qcy - 1), y1 = min(Gg - 1, qcy + 1);
    const int z0 = max(0, qcz - 1), z1 = min(Gg - 1, qcz + 1);
    const unsigned lmask_lt = (1u << lane) - 1u;

    int cand_cnt = 0;
    for (int cz = z0; cz <= z1; ++cz) {
        for (int cy = y0; cy <= y1; ++cy) {
            const int bin0 = b * CELLS + (cz * Gg + cy) * Gg + x0;
            const int s = g_start[bin0];
            const int e = g_start[bin0 + (x1 - x0) + 1];   // x-cells contiguous
            for (int base = s; base < e; base += 32) {
                const int i = base + lane;
                bool in = false;
                int pid = 0;
                if (i < e) {
                    const float4 p = g_spts[i];
                    pid = g_sidx[i];
                    // bit-identical to the passing arithmetic:
                    const float dot = __fmaf_rn(qz, p.z,
                                      __fmaf_rn(qy, p.y, __fmul_rn(qx, p.x)));
                    const float d2  = __fsub_rn(__fadd_rn(m2, p.w), __fmul_rn(2.0f, dot));
                    in = d2 < 0.01f;
                }
                const unsigned mask = __ballot_sync(0xffffffffu, in);
                if (in) {
                    const int pos = cand_cnt + __popc(mask & lmask_lt);
                    if (pos < CAP) cand[wid][pos] = pid;
                }
                cand_cnt += __popc(mask);
            }
        }
    }
    if (cand_cnt > CAP) cand_cnt = CAP;

    // 4 items per lane, lane-local ascending sort
    int a[4];
    #pragma unroll
    for (int k = 0; k < 4; ++k) {
        const int p = k * 32 + lane;
        a[k] = (p < cand_cnt) ? cand[wid][p] : SENT;
    }
    {
        int lo, hi;
        lo = min(a[0], a[1]); hi = max(a[0], a[1]); a[0] = lo; a[1] = hi;
        lo = min(a[2], a[3]); hi = max(a[2], a[3]); a[2] = lo; a[3] = hi;
        lo = min(a[0], a[2]); hi = max(a[0], a[2]); a[0] = lo; a[2] = hi;
        lo = min(a[1], a[3]); hi = max(a[1], a[3]); a[1] = lo; a[3] = hi;
        lo = min(a[1], a[2]); hi = max(a[1], a[2]); a[1] = lo; a[2] = hi;
    }
    // 32 rounds of REDUX-min extraction -> ascending indices
    #pragma unroll 1
    for (int r = 0; r < Kk; ++r) {
        const int mv = __reduce_min_sync(0xffffffffu, a[0]);
        const unsigned tie = __ballot_sync(0xffffffffu, a[0] == mv);
        if (lane == (int)(__ffs(tie) - 1)) {
            a[0] = a[1]; a[1] = a[2]; a[2] = a[3]; a[3] = SENT;
        }
        if (lane == 0) idx_sh[wid][r] = mv;
    }
    __syncwarp();
    {   // pad: sentinel -> first (or 0 if empty)
        int v = idx_sh[wid][lane];
        int first = idx_sh[wid][0];
        first = (first >= Nn) ? 0 : first;
        v = (v >= Nn) ? first : v;
        __syncwarp();
        idx_sh[wid][lane] = v;
    }
    __syncthreads();

    // ---- OUTPUT: 4 pair-iterations, 2 queries concurrently ----
    const float4* __restrict__ pts = g_pts + b * Nn;
    const float*  __restrict__ ft  = g_feat_t + (size_t)b * Nn * Cc;
    const size_t GX = (size_t)Bb * 67 * Mm * Kk;

    #pragma unroll 1
    for (int pq = 0; pq < 4; ++pq) {
        const int q0 = pq * 2;

        if (tid < 2 * Kk) {
            const int q = tid >> 5, j = tid & 31;
            const float4 p  = pts[idx_sh[q0 + q][j]];
            const float4 Qd = q_sh[q0 + q];
            g_s[q][0][j] = __fsub_rn(p.x, Qd.x);
            g_s[q][1][j] = __fsub_rn(p.y, Qd.y);
            g_s[q][2][j] = __fsub_rn(p.z, Qd.z);
        }
        // stage features: float4 loads, 256B contiguous per neighbor
        #pragma unroll
        for (int l = tid; l < 2 * Kk * 16; l += 256) {
            const int q = l >> 9, j = (l >> 4) & 31, c4 = (l & 15) * 4;
            const float4 v = *(const float4*)&ft[(size_t)idx_sh[q0 + q][j] * Cc + c4];
            f_s[q][j][c4 + 0] = v.x; f_s[q][j][c4 + 1] = v.y;
            f_s[q][j][c4 + 2] = v.z; f_s[q][j][c4 + 3] = v.w;
        }
        __syncthreads();

        // feature channels c<64: float4 writes over j
        #pragma unroll
        for (int o = tid; o < Cc * 2 * 8; o += 256) {
            const int c = o >> 4, q = (o >> 3) & 1, j4 = (o & 7) * 4;
            float4 v;
            v.x = f_s[q][j4 + 0][c]; v.y = f_s[q][j4 + 1][c];
            v.z = f_s[q][j4 + 2][c]; v.w = f_s[q][j4 + 3][c];
            *(float4*)&out[(((size_t)(b * 67 + c)) * Mm + m_base + q0 + q) * Kk + j4] = v;
        }
        // xyz channels (64..66) + appended group_xyz
        if (tid < 2 * 3 * Kk) {
            const int q = tid / 96, r = tid % 96;
            const int axis = r >> 5, j = r & 31;
            const float v = g_s[q][axis][j];
            const size_t mq = m_base + q0 + q;
            out[(((size_t)(b * 67 + 64 + axis)) * Mm + mq) * Kk + j] = v;
            out[GX + (((size_t)(b * 3 + axis)) * Mm + mq) * Kk + j] = v;
        }
        __syncthreads();   // before reusing f_s / g_s
    }
}

// ---------------------------------------------------------------------------
extern "C" void kernel_launch(void* const* d_in, const int* in_sizes, int n_in,
                              void* d_out, int out_size) {
    const float* new_xyz = (const float*)d_in[0];   // (8, 3, 2048)
    const float* xyz     = (const float*)d_in[1];   // (8, 3, 8192)
    const float* feat    = (const float*)d_in[2];   // (8, 64, 8192)
    float* out = (float*)d_out;

    zero_kernel<<<(BINS + 255) / 256, 256>>>();
    prep_transpose_kernel<<<TP_BLOCKS + NPTS / 256, 256>>>(xyz, feat);
    scan_kernel<<<1, 256>>>();
    scatter_kernel<<<(NPTS + 255) / 256, 256>>>();
    group_kernel<<<dim3(Mm / 8, Bb), 256>>>(new_xyz, out);
}

// round 8
// speedup vs baseline: 2.9878x; 1.0483x over previous
#include <cuda_runtime.h>
#include <cuda_bf16.h>

// Problem constants (fixed by dataset)
constexpr int Bb = 8;
constexpr int Nn = 8192;
constexpr int Mm = 2048;
constexpr int Cc = 64;
constexpr int Kk = 32;

// Spatial grid: 8x8x8 cells of 0.125 (>= radius 0.1 -> 27-cell neighborhood exact)
constexpr int Gg    = 8;
constexpr int CELLS = Gg * Gg * Gg;        // 512
constexpr int BINS  = Bb * CELLS;          // 4096
constexpr int NPTS  = Bb * Nn;             // 65536
constexpr int CAP   = 128;                 // max hits/query (lambda~34)
constexpr int SENT  = 0x3FFFFFFF;

// Scratch (__device__ globals: no allocs allowed; zero-initialized at load)
__device__ float  g_feat_t[Bb * Nn * Cc];            // transposed features (B,N,C)
__device__ float4 g_pts[NPTS];                       // (x,y,z,n2) original order
__device__ int    g_binid[NPTS];                     // rank<<12 | bin
__device__ __align__(16) int g_cnt[BINS];            // histogram; re-zeroed by scan
__device__ __align__(16) int g_start[BINS + 4];      // padded for int4 stores
__device__ float4 g_spts[NPTS];                      // grid-sorted (x,y,z,pid)

// ---------------------------------------------------------------------------
// Fused: blocks [0, 1024) transpose feature (B,C,N)->(B,N,C) in 64x64 tiles;
// blocks [1024, 1280) pack points (x,y,z,n2) + histogram (rank from atomicAdd).
// ---------------------------------------------------------------------------
constexpr int TP_BLOCKS = (Nn / 64) * Bb;   // 1024

__global__ __launch_bounds__(256) void prep_transpose_kernel(
    const float* __restrict__ xyz, const float* __restrict__ feat)
{
    __shared__ float tile[64][65];
    const int t = threadIdx.x;

    if (blockIdx.x < TP_BLOCKS) {
        const int b  = blockIdx.x >> 7;
        const int n0 = (blockIdx.x & 127) * 64;
        const int j4 = (t & 15) * 4;
        #pragma unroll
        for (int p = 0; p < 4; ++p) {
            const int row = p * 16 + (t >> 4);     // channel
            const float4 v = *(const float4*)&feat[((size_t)(b * Cc + row)) * Nn + n0 + j4];
            tile[row][j4 + 0] = v.x; tile[row][j4 + 1] = v.y;
            tile[row][j4 + 2] = v.z; tile[row][j4 + 3] = v.w;
        }
        __syncthreads();
        #pragma unroll
        for (int p = 0; p < 4; ++p) {
            const int r = p * 16 + (t >> 4);       // point within tile
            float4 v;
            v.x = tile[j4 + 0][r]; v.y = tile[j4 + 1][r];
            v.z = tile[j4 + 2][r]; v.w = tile[j4 + 3][r];
            *(float4*)&g_feat_t[((size_t)(b * Nn + n0 + r)) * Cc + j4] = v;
        }
    } else {
        const int i = (blockIdx.x - TP_BLOCKS) * 256 + t;   // 0 .. NPTS-1
        const int b = i >> 13;
        const int n = i & (Nn - 1);
        const float x = xyz[(b * 3 + 0) * Nn + n];
        const float y = xyz[(b * 3 + 1) * Nn + n];
        const float z = xyz[(b * 3 + 2) * Nn + n];
        const float n2 = __fadd_rn(__fadd_rn(__fmul_rn(x, x), __fmul_rn(y, y)),
                                   __fmul_rn(z, z));
        g_pts[i] = make_float4(x, y, z, n2);
        const int cx = min(Gg - 1, max(0, (int)(x * Gg)));
        const int cy = min(Gg - 1, max(0, (int)(y * Gg)));
        const int cz = min(Gg - 1, max(0, (int)(z * Gg)));
        const int bin = b * CELLS + ((cz * Gg + cy) * Gg + cx);
        const int rank = atomicAdd(&g_cnt[bin], 1);   // rank doubles as scatter slot
        g_binid[i] = (rank << 12) | bin;
    }
}

// ---------------------------------------------------------------------------
// Exclusive scan of 4096 bins (256 thr x 16, int4); re-zeroes g_cnt for the
// next run (graph replays re-execute the whole sequence).
// ---------------------------------------------------------------------------
__global__ __launch_bounds__(256) void scan_kernel() {
    __shared__ int wsum[8];
    const int t = threadIdx.x, lane = t & 31, w = t >> 5;
    int vals[16];
    #pragma unroll
    for (int k = 0; k < 4; ++k) {
        const int4 v = *(const int4*)&g_cnt[t * 16 + k * 4];
        vals[k * 4 + 0] = v.x; vals[k * 4 + 1] = v.y;
        vals[k * 4 + 2] = v.z; vals[k * 4 + 3] = v.w;
    }
    #pragma unroll
    for (int k = 0; k < 4; ++k)
        *(int4*)&g_cnt[t * 16 + k * 4] = make_int4(0, 0, 0, 0);
    int sum = 0;
    int pre[16];
    #pragma unroll
    for (int k = 0; k < 16; ++k) { pre[k] = sum; sum += vals[k]; }
    int incl = sum;
    #pragma unroll
    for (int off = 1; off < 32; off <<= 1) {
        const int x = __shfl_up_sync(0xffffffffu, incl, off);
        if (lane >= off) incl += x;
    }
    if (lane == 31) wsum[w] = incl;
    __syncthreads();
    if (t == 0) {
        int acc = 0;
        #pragma unroll
        for (int i = 0; i < 8; ++i) { const int x = wsum[i]; wsum[i] = acc; acc += x; }
        g_start[BINS] = acc;
    }
    __syncthreads();
    const int excl = wsum[w] + incl - sum;
    #pragma unroll
    for (int k = 0; k < 4; ++k) {
        int4 o;
        o.x = excl + pre[k * 4 + 0]; o.y = excl + pre[k * 4 + 1];
        o.z = excl + pre[k * 4 + 2]; o.w = excl + pre[k * 4 + 3];
        *(int4*)&g_start[t * 16 + k * 4] = o;
    }
}

// Atomic-free scatter: slot = g_start[bin] + rank (rank captured in prep).
// 2 points per thread for MLP; pid packed into spts.w.
__global__ __launch_bounds__(256) void scatter_kernel() {
    const int t0 = blockIdx.x * blockDim.x + threadIdx.x;
    #pragma unroll
    for (int k = 0; k < 2; ++k) {
        const int t = t0 + k * (NPTS / 2);
        const int br = g_binid[t];
        const int pos = g_start[br & 4095] + (br >> 12);
        float4 p = g_pts[t];
        p.w = __int_as_float(t & (Nn - 1));
        g_spts[pos] = p;
    }
}

// ---------------------------------------------------------------------------
// Fused select + output. Block = 256 thr = 8 warps = 8 queries.
// Select: warp-per-query grid-pruned exact ball query + REDUX-min extraction.
// Output: 4 pair-iterations, 2 queries concurrently; streaming stores.
// ---------------------------------------------------------------------------
__global__ __launch_bounds__(256) void group_kernel(
    const float* __restrict__ new_xyz,
    float* __restrict__ out)
{
    const int b      = blockIdx.y;
    const int m_base = blockIdx.x * 8;
    const int tid    = threadIdx.x;
    const int wid    = tid >> 5;
    const int lane   = tid & 31;

    __shared__ int    cand[8][CAP];
    __shared__ int    idx_sh[8][Kk];
    __shared__ float4 q_sh[8];
    __shared__ float  g_s[2][3][Kk];
    __shared__ float  f_s[2][Kk][Cc + 1];

    // ---- SELECT (warp <-> query) ----
    const int m = m_base + wid;
    const float qx = new_xyz[(b * 3 + 0) * Mm + m];
    const float qy = new_xyz[(b * 3 + 1) * Mm + m];
    const float qz = new_xyz[(b * 3 + 2) * Mm + m];
    const float m2 = __fadd_rn(__fadd_rn(__fmul_rn(qx, qx), __fmul_rn(qy, qy)),
                               __fmul_rn(qz, qz));
    if (lane == 0) q_sh[wid] = make_float4(qx, qy, qz, m2);

    const int qcx = min(Gg - 1, max(0, (int)(qx * Gg)));
    const int qcy = min(Gg - 1, max(0, (int)(qy * Gg)));
    const int qcz = min(Gg - 1, max(0, (int)(qz * Gg)));
    const int x0 = max(0, qcx - 1), x1 = min(Gg - 1, qcx + 1);
    const int y0 = max(0, qcy - 1), y1 = min(Gg - 1, qcy + 1);
    const int z0 = max(0, qcz - 1), z1 = min(Gg - 1, qcz + 1);
    const unsigned lmask_lt = (1u << lane) - 1u;

    int cand_cnt = 0;
    for (int cz = z0; cz <= z1; ++cz) {
        for (int cy = y0; cy <= y1; ++cy) {
            const int bin0 = b * CELLS + (cz * Gg + cy) * Gg + x0;
            const int s = g_start[bin0];
            const int e = g_start[bin0 + (x1 - x0) + 1];   // x-cells contiguous
            for (int base = s; base < e; base += 32) {
                const int i = base + lane;
                bool in = false;
                int pid = 0;
                if (i < e) {
                    const float4 p = g_spts[i];
                    pid = __float_as_int(p.w);
                    // n2 recomputed with the exact reference rounding chain
                    const float n2 = __fadd_rn(__fadd_rn(__fmul_rn(p.x, p.x),
                                                         __fmul_rn(p.y, p.y)),
                                               __fmul_rn(p.z, p.z));
                    const float dot = __fmaf_rn(qz, p.z,
                                      __fmaf_rn(qy, p.y, __fmul_rn(qx, p.x)));
                    const float d2  = __fsub_rn(__fadd_rn(m2, n2), __fmul_rn(2.0f, dot));
                    in = d2 < 0.01f;
                }
                const unsigned mask = __ballot_sync(0xffffffffu, in);
                if (in) {
                    const int pos = cand_cnt + __popc(mask & lmask_lt);
                    if (pos < CAP) cand[wid][pos] = pid;
                }
                cand_cnt += __popc(mask);
            }
        }
    }
    if (cand_cnt > CAP) cand_cnt = CAP;

    // 4 items per lane, lane-local ascending sort
    int a[4];
    #pragma unroll
    for (int k = 0; k < 4; ++k) {
        const int p = k * 32 + lane;
        a[k] = (p < cand_cnt) ? cand[wid][p] : SENT;
    }
    {
        int lo, hi;
        lo = min(a[0], a[1]); hi = max(a[0], a[1]); a[0] = lo; a[1] = hi;
        lo = min(a[2], a[3]); hi = max(a[2], a[3]); a[2] = lo; a[3] = hi;
        lo = min(a[0], a[2]); hi = max(a[0], a[2]); a[0] = lo; a[2] = hi;
        lo = min(a[1], a[3]); hi = max(a[1], a[3]); a[1] = lo; a[3] = hi;
        lo = min(a[1], a[2]); hi = max(a[1], a[2]); a[1] = lo; a[2] = hi;
    }
    // 32 rounds of REDUX-min extraction -> ascending indices
    #pragma unroll 1
    for (int r = 0; r < Kk; ++r) {
        const int mv = __reduce_min_sync(0xffffffffu, a[0]);
        const unsigned tie = __ballot_sync(0xffffffffu, a[0] == mv);
        if (lane == (int)(__ffs(tie) - 1)) {
            a[0] = a[1]; a[1] = a[2]; a[2] = a[3]; a[3] = SENT;
        }
        if (lane == 0) idx_sh[wid][r] = mv;
    }
    __syncwarp();
    {   // pad: sentinel -> first (or 0 if empty)
        int v = idx_sh[wid][lane];
        int first = idx_sh[wid][0];
        first = (first >= Nn) ? 0 : first;
        v = (v >= Nn) ? first : v;
        __syncwarp();
        idx_sh[wid][lane] = v;
    }
    __syncthreads();

    // ---- OUTPUT: 4 pair-iterations, 2 queries concurrently ----
    const float4* __restrict__ pts = g_pts + b * Nn;
    const float*  __restrict__ ft  = g_feat_t + (size_t)b * Nn * Cc;
    const size_t GX = (size_t)Bb * 67 * Mm * Kk;

    #pragma unroll 1
    for (int pq = 0; pq < 4; ++pq) {
        const int q0 = pq * 2;

        if (tid < 2 * Kk) {
            const int q = tid >> 5, j = tid & 31;
            const float4 p  = pts[idx_sh[q0 + q][j]];
            const float4 Qd = q_sh[q0 + q];
            g_s[q][0][j] = __fsub_rn(p.x, Qd.x);
            g_s[q][1][j] = __fsub_rn(p.y, Qd.y);
            g_s[q][2][j] = __fsub_rn(p.z, Qd.z);
        }
        // stage features: float4 loads, 256B contiguous per neighbor
        #pragma unroll
        for (int l = tid; l < 2 * Kk * 16; l += 256) {
            const int q = l >> 9, j = (l >> 4) & 31, c4 = (l & 15) * 4;
            const float4 v = *(const float4*)&ft[(size_t)idx_sh[q0 + q][j] * Cc + c4];
            f_s[q][j][c4 + 0] = v.x; f_s[q][j][c4 + 1] = v.y;
            f_s[q][j][c4 + 2] = v.z; f_s[q][j][c4 + 3] = v.w;
        }
        __syncthreads();

        // feature channels c<64: float4 streaming writes over j
        #pragma unroll
        for (int o = tid; o < Cc * 2 * 8; o += 256) {
            const int c = o >> 4, q = (o >> 3) & 1, j4 = (o & 7) * 4;
            float4 v;
            v.x = f_s[q][j4 + 0][c]; v.y = f_s[q][j4 + 1][c];
            v.z = f_s[q][j4 + 2][c]; v.w = f_s[q][j4 + 3][c];
            __stcs((float4*)&out[(((size_t)(b * 67 + c)) * Mm + m_base + q0 + q) * Kk + j4], v);
        }
        // xyz channels (64..66) + appended group_xyz
        if (tid < 2 * 3 * Kk) {
            const int q = tid / 96, r = tid % 96;
            const int axis = r >> 5, j = r & 31;
            const float v = g_s[q][axis][j];
            const size_t mq = m_base + q0 + q;
            __stcs(&out[(((size_t)(b * 67 + 64 + axis)) * Mm + mq) * Kk + j], v);
            __stcs(&out[GX + (((size_t)(b * 3 + axis)) * Mm + mq) * Kk + j], v);
        }
        __syncthreads();   // before reusing f_s / g_s
    }
}

// ---------------------------------------------------------------------------
extern "C" void kernel_launch(void* const* d_in, const int* in_sizes, int n_in,
                              void* d_out, int out_size) {
    const float* new_xyz = (const float*)d_in[0];   // (8, 3, 2048)
    const float* xyz     = (const float*)d_in[1];   // (8, 3, 8192)
    const float* feat    = (const float*)d_in[2];   // (8, 64, 8192)
    float* out = (float*)d_out;

    prep_transpose_kernel<<<TP_BLOCKS + NPTS / 256, 256>>>(xyz, feat);
    scan_kernel<<<1, 256>>>();
    scatter_kernel<<<(NPTS / 2) / 256, 256>>>();
    group_kernel<<<dim3(Mm / 8, Bb), 256>>>(new_xyz, out);
}

// round 9
// speedup vs baseline: 3.3755x; 1.1298x over previous
#include <cuda_runtime.h>
#include <cuda_bf16.h>

// Problem constants (fixed by dataset)
constexpr int Bb = 8;
constexpr int Nn = 8192;
constexpr int Mm = 2048;
constexpr int Cc = 64;
constexpr int Kk = 32;

// Spatial grid: 8x8x8 cells of 0.125 (>= radius 0.1 -> 27-cell neighborhood exact)
constexpr int Gg    = 8;
constexpr int CELLS = Gg * Gg * Gg;        // 512
constexpr int BINS  = Bb * CELLS;          // 4096
constexpr int NPTS  = Bb * Nn;             // 65536
constexpr int CAP   = 128;                 // max hits/query (lambda~34)
constexpr int SENT  = 0x3FFFFFFF;

// Scratch (__device__ globals: no allocs allowed; zero-initialized at load)
__device__ float  g_feat_t[Bb * Nn * Cc];            // transposed features (B,N,C)
__device__ float4 g_pts[NPTS];                       // (x,y,z,n2) original order
__device__ int    g_binid[NPTS];                     // rank<<12 | bin
__device__ __align__(16) int g_cnt[BINS];            // histogram; re-zeroed by scan
__device__ __align__(16) int g_start[BINS + 4];      // padded for int4 stores
__device__ float4 g_spts[NPTS];                      // grid-sorted (x,y,z,pid)

// ---------------------------------------------------------------------------
// Fused: blocks [0, 1024) transpose feature (B,C,N)->(B,N,C) in 64x64 tiles;
// blocks [1024, 1280) pack points (x,y,z,n2) + histogram (rank from atomicAdd).
// ---------------------------------------------------------------------------
constexpr int TP_BLOCKS = (Nn / 64) * Bb;   // 1024

__global__ __launch_bounds__(256) void prep_transpose_kernel(
    const float* __restrict__ xyz, const float* __restrict__ feat)
{
    __shared__ float tile[64][65];
    const int t = threadIdx.x;

    if (blockIdx.x < TP_BLOCKS) {
        const int b  = blockIdx.x >> 7;
        const int n0 = (blockIdx.x & 127) * 64;
        const int j4 = (t & 15) * 4;
        #pragma unroll
        for (int p = 0; p < 4; ++p) {
            const int row = p * 16 + (t >> 4);     // channel
            const float4 v = *(const float4*)&feat[((size_t)(b * Cc + row)) * Nn + n0 + j4];
            tile[row][j4 + 0] = v.x; tile[row][j4 + 1] = v.y;
            tile[row][j4 + 2] = v.z; tile[row][j4 + 3] = v.w;
        }
        __syncthreads();
        #pragma unroll
        for (int p = 0; p < 4; ++p) {
            const int r = p * 16 + (t >> 4);       // point within tile
            float4 v;
            v.x = tile[j4 + 0][r]; v.y = tile[j4 + 1][r];
            v.z = tile[j4 + 2][r]; v.w = tile[j4 + 3][r];
            *(float4*)&g_feat_t[((size_t)(b * Nn + n0 + r)) * Cc + j4] = v;
        }
    } else {
        const int i = (blockIdx.x - TP_BLOCKS) * 256 + t;   // 0 .. NPTS-1
        const int b = i >> 13;
        const int n = i & (Nn - 1);
        const float x = xyz[(b * 3 + 0) * Nn + n];
        const float y = xyz[(b * 3 + 1) * Nn + n];
        const float z = xyz[(b * 3 + 2) * Nn + n];
        const float n2 = __fadd_rn(__fadd_rn(__fmul_rn(x, x), __fmul_rn(y, y)),
                                   __fmul_rn(z, z));
        g_pts[i] = make_float4(x, y, z, n2);
        const int cx = min(Gg - 1, max(0, (int)(x * Gg)));
        const int cy = min(Gg - 1, max(0, (int)(y * Gg)));
        const int cz = min(Gg - 1, max(0, (int)(z * Gg)));
        const int bin = b * CELLS + ((cz * Gg + cy) * Gg + cx);
        const int rank = atomicAdd(&g_cnt[bin], 1);   // rank doubles as scatter slot
        g_binid[i] = (rank << 12) | bin;
    }
}

// ---------------------------------------------------------------------------
// Exclusive scan of 4096 bins (256 thr x 16, int4); re-zeroes g_cnt for the
// next run (graph replays re-execute the whole sequence).
// ---------------------------------------------------------------------------
__global__ __launch_bounds__(256) void scan_kernel() {
    __shared__ int wsum[8];
    const int t = threadIdx.x, lane = t & 31, w = t >> 5;
    int vals[16];
    #pragma unroll
    for (int k = 0; k < 4; ++k) {
        const int4 v = *(const int4*)&g_cnt[t * 16 + k * 4];
        vals[k * 4 + 0] = v.x; vals[k * 4 + 1] = v.y;
        vals[k * 4 + 2] = v.z; vals[k * 4 + 3] = v.w;
    }
    #pragma unroll
    for (int k = 0; k < 4; ++k)
        *(int4*)&g_cnt[t * 16 + k * 4] = make_int4(0, 0, 0, 0);
    int sum = 0;
    int pre[16];
    #pragma unroll
    for (int k = 0; k < 16; ++k) { pre[k] = sum; sum += vals[k]; }
    int incl = sum;
    #pragma unroll
    for (int off = 1; off < 32; off <<= 1) {
        const int x = __shfl_up_sync(0xffffffffu, incl, off);
        if (lane >= off) incl += x;
    }
    if (lane == 31) wsum[w] = incl;
    __syncthreads();
    if (t == 0) {
        int acc = 0;
        #pragma unroll
        for (int i = 0; i < 8; ++i) { const int x = wsum[i]; wsum[i] = acc; acc += x; }
        g_start[BINS] = acc;
    }
    __syncthreads();
    const int excl = wsum[w] + incl - sum;
    #pragma unroll
    for (int k = 0; k < 4; ++k) {
        int4 o;
        o.x = excl + pre[k * 4 + 0]; o.y = excl + pre[k * 4 + 1];
        o.z = excl + pre[k * 4 + 2]; o.w = excl + pre[k * 4 + 3];
        *(int4*)&g_start[t * 16 + k * 4] = o;
    }
}

// Atomic-free scatter: slot = g_start[bin] + rank (rank captured in prep).
// 2 points per thread for MLP; pid packed into spts.w.
__global__ __launch_bounds__(256) void scatter_kernel() {
    const int t0 = blockIdx.x * blockDim.x + threadIdx.x;
    #pragma unroll
    for (int k = 0; k < 2; ++k) {
        const int t = t0 + k * (NPTS / 2);
        const int br = g_binid[t];
        const int pos = g_start[br & 4095] + (br >> 12);
        float4 p = g_pts[t];
        p.w = __int_as_float(t & (Nn - 1));
        g_spts[pos] = p;
    }
}

// ---------------------------------------------------------------------------
// Fused select + output. Block = 256 thr = 8 warps = 8 queries.
// Select: warp-per-query grid-pruned exact ball query + warp bitonic sort-128.
// Output: 4 pair-iterations, 2 queries concurrently; streaming stores.
// ---------------------------------------------------------------------------
__global__ __launch_bounds__(256) void group_kernel(
    const float* __restrict__ new_xyz,
    float* __restrict__ out)
{
    const int b      = blockIdx.y;
    const int m_base = blockIdx.x * 8;
    const int tid    = threadIdx.x;
    const int wid    = tid >> 5;
    const int lane   = tid & 31;

    __shared__ int    cand[8][CAP];
    __shared__ int    idx_sh[8][Kk];
    __shared__ float4 q_sh[8];
    __shared__ float  g_s[2][3][Kk];
    __shared__ float  f_s[2][Kk][Cc + 1];

    // ---- SELECT (warp <-> query) ----
    const int m = m_base + wid;
    const float qx = new_xyz[(b * 3 + 0) * Mm + m];
    const float qy = new_xyz[(b * 3 + 1) * Mm + m];
    const float qz = new_xyz[(b * 3 + 2) * Mm + m];
    const float m2 = __fadd_rn(__fadd_rn(__fmul_rn(qx, qx), __fmul_rn(qy, qy)),
                               __fmul_rn(qz, qz));
    if (lane == 0) q_sh[wid] = make_float4(qx, qy, qz, m2);

    const int qcx = min(Gg - 1, max(0, (int)(qx * Gg)));
    const int qcy = min(Gg - 1, max(0, (int)(qy * Gg)));
    const int qcz = min(Gg - 1, max(0, (int)(qz * Gg)));
    const int x0 = max(0, qcx - 1), x1 = min(Gg - 1, qcx + 1);
    const int y0 = max(0, qcy - 1), y1 = min(Gg - 1, qcy + 1);
    const int z0 = max(0, qcz - 1), z1 = min(Gg - 1, qcz + 1);
    const unsigned lmask_lt = (1u << lane) - 1u;

    int cand_cnt = 0;
    for (int cz = z0; cz <= z1; ++cz) {
        for (int cy = y0; cy <= y1; ++cy) {
            const int bin0 = b * CELLS + (cz * Gg + cy) * Gg + x0;
            const int s = g_start[bin0];
            const int e = g_start[bin0 + (x1 - x0) + 1];   // x-cells contiguous
            for (int base = s; base < e; base += 32) {
                const int i = base + lane;
                bool in = false;
                int pid = 0;
                if (i < e) {
                    const float4 p = g_spts[i];
                    pid = __float_as_int(p.w);
                    // n2 recomputed with the exact reference rounding chain
                    const float n2 = __fadd_rn(__fadd_rn(__fmul_rn(p.x, p.x),
                                                         __fmul_rn(p.y, p.y)),
                                               __fmul_rn(p.z, p.z));
                    const float dot = __fmaf_rn(qz, p.z,
                                      __fmaf_rn(qy, p.y, __fmul_rn(qx, p.x)));
                    const float d2  = __fsub_rn(__fadd_rn(m2, n2), __fmul_rn(2.0f, dot));
                    in = d2 < 0.01f;
                }
                const unsigned mask = __ballot_sync(0xffffffffu, in);
                if (in) {
                    const int pos = cand_cnt + __popc(mask & lmask_lt);
                    if (pos < CAP) cand[wid][pos] = pid;
                }
                cand_cnt += __popc(mask);
            }
        }
    }
    if (cand_cnt > CAP) cand_cnt = CAP;

    // ---- Warp bitonic sort of 128 values (4/lane, blocked: i = lane*4+k) ----
    int a[4];
    #pragma unroll
    for (int k = 0; k < 4; ++k) {
        const int p = lane * 4 + k;
        a[k] = (p < cand_cnt) ? cand[wid][p] : SENT;
    }
    {   // lane-local sort-4 ascending (replaces bitonic sizes 2 and 4)
        int lo, hi;
        lo = min(a[0], a[1]); hi = max(a[0], a[1]); a[0] = lo; a[1] = hi;
        lo = min(a[2], a[3]); hi = max(a[2], a[3]); a[2] = lo; a[3] = hi;
        lo = min(a[0], a[2]); hi = max(a[0], a[2]); a[0] = lo; a[2] = hi;
        lo = min(a[1], a[3]); hi = max(a[1], a[3]); a[1] = lo; a[3] = hi;
        lo = min(a[1], a[2]); hi = max(a[1], a[2]); a[1] = lo; a[2] = hi;
        if (lane & 1) {   // odd lanes descending -> alternating 4-runs
            int t0 = a[0]; a[0] = a[3]; a[3] = t0;
            int t1 = a[1]; a[1] = a[2]; a[2] = t1;
        }
    }
    #pragma unroll
    for (int size = 8; size <= 128; size <<= 1) {
        const bool dirUp = (lane & (size >> 2)) == 0;   // (i & size) == 0
        #pragma unroll
        for (int stride = size >> 1; stride >= 4; stride >>= 1) {
            const int  xl      = stride >> 2;
            const bool keepMin = (dirUp == ((lane & xl) == 0));
            #pragma unroll
            for (int k = 0; k < 4; ++k) {
                const int w = __shfl_xor_sync(0xffffffffu, a[k], xl);
                a[k] = keepMin ? min(a[k], w) : max(a[k], w);
            }
        }
        {   // stride 2: pairs (0,2),(1,3)
            int lo0 = min(a[0], a[2]), hi0 = max(a[0], a[2]);
            int lo1 = min(a[1], a[3]), hi1 = max(a[1], a[3]);
            a[0] = dirUp ? lo0 : hi0;  a[2] = dirUp ? hi0 : lo0;
            a[1] = dirUp ? lo1 : hi1;  a[3] = dirUp ? hi1 : lo1;
        }
        {   // stride 1: pairs (0,1),(2,3)
            int lo0 = min(a[0], a[1]), hi0 = max(a[0], a[1]);
            int lo1 = min(a[2], a[3]), hi1 = max(a[2], a[3]);
            a[0] = dirUp ? lo0 : hi0;  a[1] = dirUp ? hi0 : lo0;
            a[2] = dirUp ? lo1 : hi1;  a[3] = dirUp ? hi1 : lo1;
        }
    }
    // Fully ascending: smallest 32 live in lanes 0-7. Pad + publish.
    {
        int first = __shfl_sync(0xffffffffu, a[0], 0);
        first = (first >= Nn) ? 0 : first;
        if (lane < 8) {
            #pragma unroll
            for (int k = 0; k < 4; ++k) {
                const int v = (a[k] >= Nn) ? first : a[k];
                idx_sh[wid][lane * 4 + k] = v;
            }
        }
    }
    __syncthreads();

    // ---- OUTPUT: 4 pair-iterations, 2 queries concurrently ----
    const float4* __restrict__ pts = g_pts + b * Nn;
    const float*  __restrict__ ft  = g_feat_t + (size_t)b * Nn * Cc;
    const size_t GX = (size_t)Bb * 67 * Mm * Kk;

    #pragma unroll 1
    for (int pq = 0; pq < 4; ++pq) {
        const int q0 = pq * 2;

        if (tid < 2 * Kk) {
            const int q = tid >> 5, j = tid & 31;
            const float4 p  = pts[idx_sh[q0 + q][j]];
            const float4 Qd = q_sh[q0 + q];
            g_s[q][0][j] = __fsub_rn(p.x, Qd.x);
            g_s[q][1][j] = __fsub_rn(p.y, Qd.y);
            g_s[q][2][j] = __fsub_rn(p.z, Qd.z);
        }
        // stage features: float4 loads, 256B contiguous per neighbor
        #pragma unroll
        for (int l = tid; l < 2 * Kk * 16; l += 256) {
            const int q = l >> 9, j = (l >> 4) & 31, c4 = (l & 15) * 4;
            const float4 v = *(const float4*)&ft[(size_t)idx_sh[q0 + q][j] * Cc + c4];
            f_s[q][j][c4 + 0] = v.x; f_s[q][j][c4 + 1] = v.y;
            f_s[q][j][c4 + 2] = v.z; f_s[q][j][c4 + 3] = v.w;
        }
        __syncthreads();

        // feature channels c<64: float4 streaming writes over j
        #pragma unroll
        for (int o = tid; o < Cc * 2 * 8; o += 256) {
            const int c = o >> 4, q = (o >> 3) & 1, j4 = (o & 7) * 4;
            float4 v;
            v.x = f_s[q][j4 + 0][c]; v.y = f_s[q][j4 + 1][c];
            v.z = f_s[q][j4 + 2][c]; v.w = f_s[q][j4 + 3][c];
            __stcs((float4*)&out[(((size_t)(b * 67 + c)) * Mm + m_base + q0 + q) * Kk + j4], v);
        }
        // xyz channels (64..66) + appended group_xyz
        if (tid < 2 * 3 * Kk) {
            const int q = tid / 96, r = tid % 96;
            const int axis = r >> 5, j = r & 31;
            const float v = g_s[q][axis][j];
            const size_t mq = m_base + q0 + q;
            __stcs(&out[(((size_t)(b * 67 + 64 + axis)) * Mm + mq) * Kk + j], v);
            __stcs(&out[GX + (((size_t)(b * 3 + axis)) * Mm + mq) * Kk + j], v);
        }
        __syncthreads();   // before reusing f_s / g_s
    }
}

// ---------------------------------------------------------------------------
extern "C" void kernel_launch(void* const* d_in, const int* in_sizes, int n_in,
                              void* d_out, int out_size) {
    const float* new_xyz = (const float*)d_in[0];   // (8, 3, 2048)
    const float* xyz     = (const float*)d_in[1];   // (8, 3, 8192)
    const float* feat    = (const float*)d_in[2];   // (8, 64, 8192)
    float* out = (float*)d_out;

    prep_transpose_kernel<<<TP_BLOCKS + NPTS / 256, 256>>>(xyz, feat);
    scan_kernel<<<1, 256>>>();
    scatter_kernel<<<(NPTS / 2) / 256, 256>>>();
    group_kernel<<<dim3(Mm / 8, Bb), 256>>>(new_xyz, out);
}